// round 9
// baseline (speedup 1.0000x reference)
#include <cuda_runtime.h>
#include <cuda_bf16.h>
#include <math.h>
#include <stdint.h>

// Problem constants
#define NB    4
#define CIN   1024
#define CINT  512
#define HH    96
#define WW    96
#define PP    (HH * WW)      // 9216
#define DD    4
#define QQ    81
#define CSPLIT 2             // corr channel split
#define ASPLIT 8             // assemble channel split

// ---------------------------------------------------------------------------
// Scratch (device globals; no allocation allowed)
// ---------------------------------------------------------------------------
__device__ __align__(128) __nv_bfloat16 g_xb   [NB * CIN  * PP];
__device__ __align__(128) __nv_bfloat16 g_xrefb[NB * CIN  * PP];
__device__ __align__(128) __nv_bfloat16 g_wb   [4 * CINT * CIN];   // theta,g,phi,out
__device__ __align__(128) float g_theta [NB * CINT * PP];
__device__ __align__(128) float g_g     [NB * CINT * PP];
__device__ __align__(128) float g_phi   [NB * CINT * PP];
__device__ __align__(128) float g_pwpart[CSPLIT * NB * QQ * PP];
__device__ __align__(128) float g_pw    [NB * QQ * PP];
__device__ __align__(128) __nv_bfloat16 g_yb   [NB * CINT * PP];

// ---------------------------------------------------------------------------
// Helpers (legacy path: cp.async + ldmatrix + mma.sync; no tcgen05 — the
// toolchain targets sm_103 without the 'a' feature set)
// ---------------------------------------------------------------------------
__device__ __forceinline__ uint32_t sptr(const void* p) {
    return (uint32_t)__cvta_generic_to_shared(p);
}
__device__ __forceinline__ void cp16(uint32_t dst, const void* src) {
    asm volatile("cp.async.cg.shared.global [%0], [%1], 16;" :: "r"(dst), "l"(src));
}
__device__ __forceinline__ void cp_commit() {
    asm volatile("cp.async.commit_group;");
}
__device__ __forceinline__ void cp_wait0() {
    asm volatile("cp.async.wait_group 0;");
}
__device__ __forceinline__ void cp_wait1() {
    asm volatile("cp.async.wait_group 1;");
}
__device__ __forceinline__ void ldsmx4(uint32_t* r, uint32_t addr) {
    asm volatile("ldmatrix.sync.aligned.m8n8.x4.shared.b16 {%0,%1,%2,%3}, [%4];"
                 : "=r"(r[0]), "=r"(r[1]), "=r"(r[2]), "=r"(r[3]) : "r"(addr));
}
__device__ __forceinline__ void ldsmx4t(uint32_t* r, uint32_t addr) {
    asm volatile("ldmatrix.sync.aligned.m8n8.x4.trans.shared.b16 {%0,%1,%2,%3}, [%4];"
                 : "=r"(r[0]), "=r"(r[1]), "=r"(r[2]), "=r"(r[3]) : "r"(addr));
}
__device__ __forceinline__ void mma16816(float* c, const uint32_t* a, const uint32_t* b) {
    asm volatile("mma.sync.aligned.m16n8k16.row.col.f32.bf16.bf16.f32 "
                 "{%0,%1,%2,%3}, {%4,%5,%6,%7}, {%8,%9}, {%0,%1,%2,%3};"
                 : "+f"(c[0]), "+f"(c[1]), "+f"(c[2]), "+f"(c[3])
                 : "r"(a[0]), "r"(a[1]), "r"(a[2]), "r"(a[3]), "r"(b[0]), "r"(b[1]));
}

// ---------------------------------------------------------------------------
// Merged conversions: activations (z: 0=x, 1=x_ref) and weights (z: 0..3)
// ---------------------------------------------------------------------------
__global__ void __launch_bounds__(256)
convx_kernel(const float* __restrict__ x, const float* __restrict__ xref,
             __nv_bfloat16* __restrict__ xb, __nv_bfloat16* __restrict__ xrefb)
{
    const float* in = blockIdx.z ? xref : x;
    __nv_bfloat16* out = blockIdx.z ? xrefb : xb;
    int i = (blockIdx.x * 256 + threadIdx.x) * 8;
    float4 v0 = *(const float4*)(in + i);
    float4 v1 = *(const float4*)(in + i + 4);
    __nv_bfloat162 o[4];
    o[0] = __floats2bfloat162_rn(v0.x, v0.y);
    o[1] = __floats2bfloat162_rn(v0.z, v0.w);
    o[2] = __floats2bfloat162_rn(v1.x, v1.y);
    o[3] = __floats2bfloat162_rn(v1.z, v1.w);
    *(uint4*)(out + i) = *(const uint4*)o;
}

__global__ void __launch_bounds__(256)
convw_kernel(const float* __restrict__ w0, const float* __restrict__ w1,
             const float* __restrict__ w2, const float* __restrict__ w3,
             __nv_bfloat16* __restrict__ out)  // 4 contiguous WSZ segments
{
    const int z = blockIdx.z;
    const float* in = (z == 0) ? w0 : (z == 1) ? w1 : (z == 2) ? w2 : w3;
    __nv_bfloat16* o = out + (size_t)z * (CINT * CIN);
    int i = (blockIdx.x * 256 + threadIdx.x) * 8;
    float4 v0 = *(const float4*)(in + i);
    float4 v1 = *(const float4*)(in + i + 4);
    __nv_bfloat162 p[4];
    p[0] = __floats2bfloat162_rn(v0.x, v0.y);
    p[1] = __floats2bfloat162_rn(v0.z, v0.w);
    p[2] = __floats2bfloat162_rn(v1.x, v1.y);
    p[3] = __floats2bfloat162_rn(v1.z, v1.w);
    *(uint4*)(o + i) = *(const uint4*)p;
}

// ---------------------------------------------------------------------------
// bf16 tensor-core GEMM (mma.sync), round-5 pipeline, with optional split
// output (for the stacked g|phi GEMM): blocks with m0 >= msplit write O2
// using bias2, with local row (m0 - msplit). Output batch stride = Mout*P.
// ---------------------------------------------------------------------------
#define AS_STRIDE 40
#define BS_STRIDE 136
#define AS_ELEMS (128 * AS_STRIDE)
#define BS_ELEMS (32 * BS_STRIDE)
#define AS_BYTES (AS_ELEMS * 2)
#define BS_BYTES (BS_ELEMS * 2)

__global__ void __launch_bounds__(256)
bgemm_kernel(const __nv_bfloat16* __restrict__ W, const __nv_bfloat16* __restrict__ Z,
             const float* __restrict__ bias, const float* __restrict__ res,
             float* __restrict__ O, int M, int K, int P,
             const float* __restrict__ bias2, float* __restrict__ O2,
             int msplit, int Mout)
{
    __shared__ __align__(16) __nv_bfloat16 As[2 * AS_ELEMS];
    __shared__ __align__(16) __nv_bfloat16 Bs[2 * BS_ELEMS];

    const int b  = blockIdx.z;
    const __nv_bfloat16* Zb = Z + (size_t)b * K * P;
    const int m0 = blockIdx.y * 128;
    const int n0 = blockIdx.x * 128;

    const float* biasP = bias;
    float* Obase = O;
    int mrow = m0;
    if (O2 != nullptr && m0 >= msplit) { biasP = bias2; Obase = O2; mrow = m0 - msplit; }
    float* Ob = Obase + (size_t)b * Mout * P;
    const float* Rb = res ? res + (size_t)b * M * P : nullptr;

    const int tid  = threadIdx.x;
    const int lane = tid & 31;
    const int wid  = tid >> 5;
    const int wm = wid & 1;
    const int wn = wid >> 1;

    const uint32_t as0 = sptr(As);
    const uint32_t bs0 = sptr(Bs);

    const int a_r = tid >> 2;
    const int a_c = tid & 3;
    const int b_r = tid >> 4;
    const int b_c = tid & 15;

    float acc[4][4][4];
#pragma unroll
    for (int mt = 0; mt < 4; mt++)
#pragma unroll
        for (int nt = 0; nt < 4; nt++)
#pragma unroll
            for (int i = 0; i < 4; i++) acc[mt][nt][i] = 0.f;

    const int nk = K >> 5;

    {
        cp16(as0 + (uint32_t)((a_r)      * AS_STRIDE + a_c * 8) * 2, W  + (size_t)(m0 + a_r)      * K + a_c * 8);
        cp16(as0 + (uint32_t)((a_r + 64) * AS_STRIDE + a_c * 8) * 2, W  + (size_t)(m0 + a_r + 64) * K + a_c * 8);
        cp16(bs0 + (uint32_t)((b_r)      * BS_STRIDE + b_c * 8) * 2, Zb + (size_t)(b_r)      * P + n0 + b_c * 8);
        cp16(bs0 + (uint32_t)((b_r + 16) * BS_STRIDE + b_c * 8) * 2, Zb + (size_t)(b_r + 16) * P + n0 + b_c * 8);
        cp_commit();
    }

    int stage = 0;
    for (int kt = 0; kt < nk; kt++) {
        cp_wait0();
        __syncthreads();

        if (kt + 1 < nk) {
            const int k0 = (kt + 1) * 32;
            const uint32_t as = as0 + (stage ^ 1) * AS_BYTES;
            const uint32_t bs = bs0 + (stage ^ 1) * BS_BYTES;
            cp16(as + (uint32_t)((a_r)      * AS_STRIDE + a_c * 8) * 2, W  + (size_t)(m0 + a_r)      * K + k0 + a_c * 8);
            cp16(as + (uint32_t)((a_r + 64) * AS_STRIDE + a_c * 8) * 2, W  + (size_t)(m0 + a_r + 64) * K + k0 + a_c * 8);
            cp16(bs + (uint32_t)((b_r)      * BS_STRIDE + b_c * 8) * 2, Zb + (size_t)(k0 + b_r)      * P + n0 + b_c * 8);
            cp16(bs + (uint32_t)((b_r + 16) * BS_STRIDE + b_c * 8) * 2, Zb + (size_t)(k0 + b_r + 16) * P + n0 + b_c * 8);
            cp_commit();
        }

        const uint32_t as = as0 + stage * AS_BYTES;
        const uint32_t bs = bs0 + stage * BS_BYTES;

#pragma unroll
        for (int kk = 0; kk < 2; kk++) {
            const int k0 = kk * 16;
            uint32_t a[4][4];
            const uint32_t a_base = as + (uint32_t)(((wm * 64 + (lane & 15)) * AS_STRIDE) + k0 + (lane >> 4) * 8) * 2;
#pragma unroll
            for (int mt = 0; mt < 4; mt++)
                ldsmx4(a[mt], a_base + (uint32_t)(mt * 16 * AS_STRIDE) * 2);

            uint32_t bb[4][2];
            const uint32_t b_base = bs + (uint32_t)((k0 + (lane & 15)) * BS_STRIDE + wn * 32 + (lane >> 4) * 8) * 2;
            {
                uint32_t r[4];
                ldsmx4t(r, b_base);
                bb[0][0] = r[0]; bb[0][1] = r[1];
                bb[1][0] = r[2]; bb[1][1] = r[3];
                ldsmx4t(r, b_base + 16 * 2);
                bb[2][0] = r[0]; bb[2][1] = r[1];
                bb[3][0] = r[2]; bb[3][1] = r[3];
            }

#pragma unroll
            for (int mt = 0; mt < 4; mt++)
#pragma unroll
                for (int nt = 0; nt < 4; nt++)
                    mma16816(acc[mt][nt], a[mt], bb[nt]);
        }
        stage ^= 1;
        __syncthreads();
    }

#pragma unroll
    for (int mt = 0; mt < 4; mt++) {
        const int r0 = mrow + wm * 64 + mt * 16 + (lane >> 2);
        const int r1 = r0 + 8;
        const float bv0 = biasP[r0];
        const float bv1 = biasP[r1];
#pragma unroll
        for (int nt = 0; nt < 4; nt++) {
            const int col = n0 + wn * 32 + nt * 8 + (lane & 3) * 2;
            float2 v0 = make_float2(acc[mt][nt][0] + bv0, acc[mt][nt][1] + bv0);
            float2 v1 = make_float2(acc[mt][nt][2] + bv1, acc[mt][nt][3] + bv1);
            if (Rb) {
                float2 t0 = *(const float2*)&Rb[(size_t)r0 * P + col];
                float2 t1 = *(const float2*)&Rb[(size_t)r1 * P + col];
                v0.x += t0.x; v0.y += t0.y;
                v1.x += t1.x; v1.y += t1.y;
            }
            *(float2*)&Ob[(size_t)r0 * P + col] = v0;
            *(float2*)&Ob[(size_t)r1 * P + col] = v1;
        }
    }
}

// ---------------------------------------------------------------------------
// Correlation: y-pair blocking (round-5 compute) + cp.async ping-pong smem.
// Tile 32(w) x 16(h), thread (tx,ty) owns pixels (2ty,tx),(2ty+1,tx).
// Border of phi window pre-zeroed once (channel-invariant); interior streamed.
// Dynamic smem: th[2] (4096 f each) + ph[2] (7680 f each) = 92 KB.
// ---------------------------------------------------------------------------
#define CTW 32
#define CTH2 16
#define CWW (CTW + 2 * DD)    // 40
#define CWH (CTH2 + 2 * DD)   // 24
#define CCH 8
#define CPB (CINT / CSPLIT)   // 256
#define TH_ELEMS (CCH * CTH2 * CTW)   // 4096
#define PH_ELEMS (CCH * CWH * CWW)    // 7680
#define CORR_SMEM ((2 * TH_ELEMS + 2 * PH_ELEMS) * 4)   // 94208 B
#define ASM_SMEM  ((2 * PH_ELEMS) * 4)                  // 61440 B

struct WinGeom {
    int gc0, nseg, scol, rlo, nrv;
};
__device__ __forceinline__ WinGeom make_geom(int w0, int h0) {
    WinGeom g;
    int gc0 = w0 - DD; if (gc0 < 0) gc0 = 0;
    int gc1 = w0 + CTW + DD; if (gc1 > WW) gc1 = WW;
    g.gc0 = gc0;
    g.nseg = (gc1 - gc0) >> 2;            // 9 or 10 float4 segments
    g.scol = gc0 - (w0 - DD);             // 0 or 4
    g.rlo = (h0 >= DD) ? 0 : (DD - h0);
    int rhi = (h0 + CTH2 + DD <= HH) ? CWH : (HH + DD - h0);
    g.nrv = rhi - g.rlo;
    return g;
}

// Issue interior window rows (phi or g) into smem buffer via cp.async.
__device__ __forceinline__ void issue_win(uint32_t buf, const float* src_base,
                                          int c0, int h0, const WinGeom& g, int tid)
{
    const int per_cc = g.nrv * g.nseg;
    const int total = CCH * per_cc;
    for (int t = tid; t < total; t += 256) {
        int cc = t / per_cc;
        int rem = t - cc * per_cc;
        int r = rem / g.nseg;
        int s = rem - r * g.nseg;
        int row = g.rlo + r;
        int hh = h0 - DD + row;
        cp16(buf + (uint32_t)(((cc * CWH + row) * CWW + g.scol + s * 4) * 4),
             src_base + (size_t)(c0 + cc) * PP + hh * WW + g.gc0 + s * 4);
    }
}

__device__ __forceinline__ void issue_theta(uint32_t buf, const float* thb,
                                            int c0, int h0, int w0, int tid)
{
    for (int t = tid; t < CCH * CTH2 * 8; t += 256) {   // 1024 tasks
        int cc = t >> 7;
        int rem = t & 127;
        int r = rem >> 3;
        int s = rem & 7;
        cp16(buf + (uint32_t)(((cc * CTH2 + r) * CTW + s * 4) * 4),
             thb + (size_t)(c0 + cc) * PP + (h0 + r) * WW + w0 + s * 4);
    }
}

__global__ void __launch_bounds__(256, 1)
corr_kernel(const float* __restrict__ theta,
            const float* __restrict__ phi,
            float* __restrict__ pwpart)
{
    extern __shared__ float dynf[];
    float* th_s[2] = { dynf, dynf + TH_ELEMS };
    float* ph_s[2] = { dynf + 2 * TH_ELEMS, dynf + 2 * TH_ELEMS + PH_ELEMS };
    const uint32_t th_u0 = sptr(th_s[0]);
    const uint32_t th_u1 = sptr(th_s[1]);
    const uint32_t ph_u0 = sptr(ph_s[0]);
    const uint32_t ph_u1 = sptr(ph_s[1]);

    const int z  = blockIdx.z;
    const int b  = z >> 1;
    const int ci = z & 1;
    const int ch0 = ci * CPB;
    const int w0 = blockIdx.x * CTW;
    const int h0 = blockIdx.y * CTH2;
    const int tid = threadIdx.x;
    const int tx = tid & 31;
    const int ty = tid >> 5;          // 0..7 -> pixel rows 2ty, 2ty+1

    const float* thb = theta + (size_t)b * CINT * PP;
    const float* phb = phi   + (size_t)b * CINT * PP;

    const WinGeom g = make_geom(w0, h0);

    // Pre-zero both phi buffers (border zeros persist; interior overwritten).
    {
        float4 z4 = make_float4(0.f, 0.f, 0.f, 0.f);
        float4* p = (float4*)ph_s[0];
        for (int t = tid; t < (2 * PH_ELEMS) / 4; t += 256) p[t] = z4;
    }
    __syncthreads();

    float accA[QQ], accB[QQ];
#pragma unroll
    for (int q = 0; q < QQ; q++) { accA[q] = 0.f; accB[q] = 0.f; }

    const int nch = CPB / CCH;   // 32

    issue_theta(th_u0, thb, ch0, h0, w0, tid);
    issue_win(ph_u0, phb, ch0, h0, g, tid);
    cp_commit();

    for (int c = 0; c < nch; c++) {
        if (c + 1 < nch) {
            const uint32_t tb = ((c + 1) & 1) ? th_u1 : th_u0;
            const uint32_t pb = ((c + 1) & 1) ? ph_u1 : ph_u0;
            issue_theta(tb, thb, ch0 + (c + 1) * CCH, h0, w0, tid);
            issue_win(pb, phb, ch0 + (c + 1) * CCH, h0, g, tid);
            cp_commit();
            cp_wait1();
        } else {
            cp_wait0();
        }
        __syncthreads();

        const float* ths = th_s[c & 1];
        const float* phs = ph_s[c & 1];
#pragma unroll
        for (int cc = 0; cc < CCH; cc++) {
            const float t0 = ths[cc * (CTH2 * CTW) + (2 * ty)     * CTW + tx];
            const float t1 = ths[cc * (CTH2 * CTW) + (2 * ty + 1) * CTW + tx];
            const float* pr = &phs[cc * (CWH * CWW)];
#pragma unroll
            for (int rr = 0; rr < 10; rr++) {
                const float* row = &pr[(2 * ty + rr) * CWW + tx];
#pragma unroll
                for (int dx = 0; dx < 9; dx++) {
                    const float v = row[dx];
                    if (rr < 9) accA[rr * 9 + dx] += t0 * v;
                    if (rr >= 1) accB[(rr - 1) * 9 + dx] += t1 * v;
                }
            }
        }
        __syncthreads();
    }

    const int pixA = (h0 + 2 * ty) * WW + (w0 + tx);
    float* bp = pwpart + ((size_t)(ci * NB + b) * QQ) * PP;
#pragma unroll
    for (int q = 0; q < QQ; q++) {
        bp[(size_t)q * PP + pixA]      = accA[q];
        bp[(size_t)q * PP + pixA + WW] = accB[q];
    }
}

// ---------------------------------------------------------------------------
// Softmax over Q (sums the 2 channel-split partials, applies scale)
// ---------------------------------------------------------------------------
__global__ void __launch_bounds__(128)
softmax_kernel(const float* __restrict__ part, float* __restrict__ pw)
{
    const int t = blockIdx.x * 128 + threadIdx.x;
    const int b = t / PP;
    const int pix = t - b * PP;
    const size_t qp = (size_t)QQ * PP;
    const float scale = 256.0f / sqrtf((float)WW) / (float)CINT;

    float v[QQ];
    float m = -1e30f;
#pragma unroll
    for (int q = 0; q < QQ; q++) {
        const size_t off = (size_t)q * PP + pix;
        float s = part[(size_t)(0 * NB + b) * qp + off]
                + part[(size_t)(1 * NB + b) * qp + off];
        v[q] = s * scale;
        m = fmaxf(m, v[q]);
    }
    float s = 0.f;
#pragma unroll
    for (int q = 0; q < QQ; q++) { v[q] = __expf(v[q] - m); s += v[q]; }
    const float inv = 1.0f / s;
    float* pwb = pw + (size_t)b * qp + pix;
#pragma unroll
    for (int q = 0; q < QQ; q++) pwb[(size_t)q * PP] = v[q] * inv;
}

// ---------------------------------------------------------------------------
// Assemble: y-pair blocking + cp.async ping-pong g window, bf16 output.
// Dynamic smem: gs[2] (7680 f each) = 60 KB.
// ---------------------------------------------------------------------------
__global__ void __launch_bounds__(256, 1)
assemble_kernel(const float* __restrict__ pw,
                const float* __restrict__ g,
                __nv_bfloat16* __restrict__ y)
{
    extern __shared__ float dynf[];
    float* gs[2] = { dynf, dynf + PH_ELEMS };
    const uint32_t gs_u0 = sptr(gs[0]);
    const uint32_t gs_u1 = sptr(gs[1]);

    const int z  = blockIdx.z;
    const int b  = z >> 3;
    const int c0base = (z & 7) * (CINT / ASPLIT); // 64 channels
    const int w0 = blockIdx.x * CTW;
    const int h0 = blockIdx.y * CTH2;
    const int tid = threadIdx.x;
    const int tx = tid & 31;
    const int ty = tid >> 5;

    const float* gb  = g  + (size_t)b * CINT * PP;
    const float* pwb = pw + (size_t)b * QQ * PP;
    __nv_bfloat16* yb = y + (size_t)b * CINT * PP;

    const WinGeom wg = make_geom(w0, h0);

    {
        float4 z4 = make_float4(0.f, 0.f, 0.f, 0.f);
        float4* p = (float4*)gs[0];
        for (int t = tid; t < (2 * PH_ELEMS) / 4; t += 256) p[t] = z4;
    }
    __syncthreads();

    const int pixA = (h0 + 2 * ty) * WW + (w0 + tx);
    const int pixB = pixA + WW;

    float rpwA[QQ], rpwB[QQ];
#pragma unroll
    for (int q = 0; q < QQ; q++) {
        rpwA[q] = pwb[(size_t)q * PP + pixA];
        rpwB[q] = pwb[(size_t)q * PP + pixB];
    }

    const int nch = (CINT / ASPLIT) / CCH;   // 8

    issue_win(gs_u0, gb, c0base, h0, wg, tid);
    cp_commit();

    for (int c = 0; c < nch; c++) {
        if (c + 1 < nch) {
            const uint32_t bu = ((c + 1) & 1) ? gs_u1 : gs_u0;
            issue_win(bu, gb, c0base + (c + 1) * CCH, h0, wg, tid);
            cp_commit();
            cp_wait1();
        } else {
            cp_wait0();
        }
        __syncthreads();

        const float* gsb = gs[c & 1];
        const int c0 = c0base + c * CCH;
#pragma unroll
        for (int cc = 0; cc < CCH; cc++) {
            const float* gr = &gsb[cc * (CWH * CWW)];
            float aA = 0.f, aB = 0.f;
#pragma unroll
            for (int rr = 0; rr < 10; rr++) {
                const float* row = &gr[(2 * ty + rr) * CWW + tx];
#pragma unroll
                for (int dx = 0; dx < 9; dx++) {
                    const float v = row[dx];
                    if (rr < 9) aA += rpwA[rr * 9 + dx] * v;
                    if (rr >= 1) aB += rpwB[(rr - 1) * 9 + dx] * v;
                }
            }
            yb[(size_t)(c0 + cc) * PP + pixA] = __float2bfloat16(aA);
            yb[(size_t)(c0 + cc) * PP + pixB] = __float2bfloat16(aB);
        }
        __syncthreads();
    }
}

// ---------------------------------------------------------------------------
// Launch
// ---------------------------------------------------------------------------
extern "C" void kernel_launch(void* const* d_in, const int* in_sizes, int n_in,
                              void* d_out, int out_size)
{
    (void)in_sizes; (void)n_in; (void)out_size;

    const float* x       = (const float*)d_in[0];
    const float* x_ref   = (const float*)d_in[1];
    const float* w_g     = (const float*)d_in[2];
    const float* b_g     = (const float*)d_in[3];
    const float* w_theta = (const float*)d_in[4];
    const float* b_theta = (const float*)d_in[5];
    const float* w_phi   = (const float*)d_in[6];
    const float* b_phi   = (const float*)d_in[7];
    const float* w_out   = (const float*)d_in[8];
    const float* b_out   = (const float*)d_in[9];
    float* out = (float*)d_out;

    __nv_bfloat16 *xb, *xrefb, *wb, *yb;
    float *theta, *gbuf, *phi, *pwpart, *pw;
    cudaGetSymbolAddress((void**)&xb,     g_xb);
    cudaGetSymbolAddress((void**)&xrefb,  g_xrefb);
    cudaGetSymbolAddress((void**)&wb,     g_wb);
    cudaGetSymbolAddress((void**)&theta,  g_theta);
    cudaGetSymbolAddress((void**)&gbuf,   g_g);
    cudaGetSymbolAddress((void**)&phi,    g_phi);
    cudaGetSymbolAddress((void**)&pwpart, g_pwpart);
    cudaGetSymbolAddress((void**)&pw,     g_pw);
    cudaGetSymbolAddress((void**)&yb,     g_yb);

    cudaFuncSetAttribute(corr_kernel,     cudaFuncAttributeMaxDynamicSharedMemorySize, CORR_SMEM);
    cudaFuncSetAttribute(assemble_kernel, cudaFuncAttributeMaxDynamicSharedMemorySize, ASM_SMEM);

    const int WSZ = CINT * CIN;
    // Layout in g_wb: [theta | g | phi | out]  (g and phi adjacent -> stacked GEMM)
    __nv_bfloat16* wtb = wb + 0 * WSZ;
    __nv_bfloat16* wgb = wb + 1 * WSZ;
    __nv_bfloat16* wob = wb + 3 * WSZ;

    // conversions (2 launches)
    const int nx = NB * CIN * PP;
    dim3 cxg(nx / (256 * 8), 1, 2);
    convx_kernel<<<cxg, 256>>>(x, x_ref, xb, xrefb);
    dim3 cwg(WSZ / (256 * 8), 1, 4);
    convw_kernel<<<cwg, 256>>>(w_theta, w_g, w_phi, w_out, wb);

    dim3 blk(256);

    // theta GEMM (M=512)
    dim3 gt(PP / 128, CINT / 128, NB);      // (72, 4, 4)
    bgemm_kernel<<<gt, blk>>>(wtb, xb, b_theta, nullptr, theta, CINT, CIN, PP,
                              nullptr, nullptr, 1 << 30, CINT);
    // stacked g|phi GEMM (M=1024 over x_ref; rows >=512 -> phi)
    dim3 gp(PP / 128, (2 * CINT) / 128, NB); // (72, 8, 4)
    bgemm_kernel<<<gp, blk>>>(wgb, xrefb, b_g, nullptr, gbuf, 2 * CINT, CIN, PP,
                              b_phi, phi, CINT, CINT);

    // correlation partials + softmax
    dim3 cg(WW / CTW, HH / CTH2, NB * CSPLIT);   // (3, 6, 8) = 144 blocks
    corr_kernel<<<cg, blk, CORR_SMEM>>>(theta, phi, pwpart);
    softmax_kernel<<<(NB * PP) / 128, 128>>>(pwpart, pw);

    // assemble (bf16 output)
    dim3 ag(WW / CTW, HH / CTH2, NB * ASPLIT);   // (3, 6, 32) = 576 blocks
    assemble_kernel<<<ag, blk, ASM_SMEM>>>(pw, gbuf, yb);

    // final conv + residual (M=1024, K=512)
    dim3 gf(PP / 128, CIN / 128, NB);            // (72, 8, 4)
    bgemm_kernel<<<gf, blk>>>(wob, yb, b_out, x, out, CIN, CINT, PP,
                              nullptr, nullptr, 1 << 30, CIN);
}

// round 10
// speedup vs baseline: 1.4053x; 1.4053x over previous
#include <cuda_runtime.h>
#include <cuda_bf16.h>
#include <math.h>
#include <stdint.h>

// Problem constants
#define NB    4
#define CIN   1024
#define CINT  512
#define HH    96
#define WW    96
#define PP    (HH * WW)      // 9216
#define DD    4
#define QQ    81
#define CSPLIT 2             // corr channel split
#define ASPLIT 8             // assemble channel split

// ---------------------------------------------------------------------------
// Scratch (device globals; no allocation allowed)
// ---------------------------------------------------------------------------
__device__ __align__(128) __nv_bfloat16 g_xb   [NB * CIN  * PP];
__device__ __align__(128) __nv_bfloat16 g_xrefb[NB * CIN  * PP];
__device__ __align__(128) __nv_bfloat16 g_wb   [4 * CINT * CIN];   // theta,g,phi,out
__device__ __align__(128) float g_theta [NB * CINT * PP];
__device__ __align__(128) float g_g     [NB * CINT * PP];
__device__ __align__(128) float g_phi   [NB * CINT * PP];
__device__ __align__(128) float g_pwpart[CSPLIT * NB * QQ * PP];
__device__ __align__(128) float g_pw    [NB * QQ * PP];
__device__ __align__(128) __nv_bfloat16 g_yb   [NB * CINT * PP];

// ---------------------------------------------------------------------------
// Helpers (legacy path: cp.async + ldmatrix + mma.sync; no tcgen05 — the
// toolchain targets sm_103 without the 'a' feature set)
// ---------------------------------------------------------------------------
__device__ __forceinline__ uint32_t sptr(const void* p) {
    return (uint32_t)__cvta_generic_to_shared(p);
}
__device__ __forceinline__ void cp16(uint32_t dst, const void* src) {
    asm volatile("cp.async.cg.shared.global [%0], [%1], 16;" :: "r"(dst), "l"(src));
}
__device__ __forceinline__ void cp_commit() {
    asm volatile("cp.async.commit_group;");
}
__device__ __forceinline__ void cp_wait0() {
    asm volatile("cp.async.wait_group 0;");
}
__device__ __forceinline__ void cp_wait1() {
    asm volatile("cp.async.wait_group 1;");
}
__device__ __forceinline__ void ldsmx4(uint32_t* r, uint32_t addr) {
    asm volatile("ldmatrix.sync.aligned.m8n8.x4.shared.b16 {%0,%1,%2,%3}, [%4];"
                 : "=r"(r[0]), "=r"(r[1]), "=r"(r[2]), "=r"(r[3]) : "r"(addr));
}
__device__ __forceinline__ void ldsmx4t(uint32_t* r, uint32_t addr) {
    asm volatile("ldmatrix.sync.aligned.m8n8.x4.trans.shared.b16 {%0,%1,%2,%3}, [%4];"
                 : "=r"(r[0]), "=r"(r[1]), "=r"(r[2]), "=r"(r[3]) : "r"(addr));
}
__device__ __forceinline__ void mma16816(float* c, const uint32_t* a, const uint32_t* b) {
    asm volatile("mma.sync.aligned.m16n8k16.row.col.f32.bf16.bf16.f32 "
                 "{%0,%1,%2,%3}, {%4,%5,%6,%7}, {%8,%9}, {%0,%1,%2,%3};"
                 : "+f"(c[0]), "+f"(c[1]), "+f"(c[2]), "+f"(c[3])
                 : "r"(a[0]), "r"(a[1]), "r"(a[2]), "r"(a[3]), "r"(b[0]), "r"(b[1]));
}

// ---------------------------------------------------------------------------
// Merged conversions: activations (z: 0=x, 1=x_ref) and weights (z: 0..3)
// ---------------------------------------------------------------------------
__global__ void __launch_bounds__(256)
convx_kernel(const float* __restrict__ x, const float* __restrict__ xref,
             __nv_bfloat16* __restrict__ xb, __nv_bfloat16* __restrict__ xrefb)
{
    const float* in = blockIdx.z ? xref : x;
    __nv_bfloat16* out = blockIdx.z ? xrefb : xb;
    int i = (blockIdx.x * 256 + threadIdx.x) * 8;
    float4 v0 = *(const float4*)(in + i);
    float4 v1 = *(const float4*)(in + i + 4);
    __nv_bfloat162 o[4];
    o[0] = __floats2bfloat162_rn(v0.x, v0.y);
    o[1] = __floats2bfloat162_rn(v0.z, v0.w);
    o[2] = __floats2bfloat162_rn(v1.x, v1.y);
    o[3] = __floats2bfloat162_rn(v1.z, v1.w);
    *(uint4*)(out + i) = *(const uint4*)o;
}

__global__ void __launch_bounds__(256)
convw_kernel(const float* __restrict__ w0, const float* __restrict__ w1,
             const float* __restrict__ w2, const float* __restrict__ w3,
             __nv_bfloat16* __restrict__ out)  // 4 contiguous WSZ segments
{
    const int z = blockIdx.z;
    const float* in = (z == 0) ? w0 : (z == 1) ? w1 : (z == 2) ? w2 : w3;
    __nv_bfloat16* o = out + (size_t)z * (CINT * CIN);
    int i = (blockIdx.x * 256 + threadIdx.x) * 8;
    float4 v0 = *(const float4*)(in + i);
    float4 v1 = *(const float4*)(in + i + 4);
    __nv_bfloat162 p[4];
    p[0] = __floats2bfloat162_rn(v0.x, v0.y);
    p[1] = __floats2bfloat162_rn(v0.z, v0.w);
    p[2] = __floats2bfloat162_rn(v1.x, v1.y);
    p[3] = __floats2bfloat162_rn(v1.z, v1.w);
    *(uint4*)(o + i) = *(const uint4*)p;
}

// ---------------------------------------------------------------------------
// bf16 tensor-core GEMM (mma.sync), 3-stage cp.async pipeline:
// O[b][m][p] = sum_k W[m][k]*Z[b][k][p] + bias[m] (+ res[b][m][p])
// BM=BN=128, BK=32, 8 warps (2m x 4n), warp tile 64x32.
// Each tile load gets TWO compute phases of slack (issue-before-compute into
// the stage last read two tiles ago; wait_group 1 keeps one group in flight).
// Dynamic smem: A0 A1 A2 | B0 B1 B2 = 56832 B.
// ---------------------------------------------------------------------------
#define AS_STRIDE 40
#define BS_STRIDE 136
#define AS_ELEMS (128 * AS_STRIDE)   // 5120
#define BS_ELEMS (32 * BS_STRIDE)    // 4352
#define AS_BYTES (AS_ELEMS * 2)      // 10240
#define BS_BYTES (BS_ELEMS * 2)      // 8704
#define GEMM_STAGES 3
#define GEMM_SMEM (GEMM_STAGES * (AS_BYTES + BS_BYTES))   // 56832

__global__ void __launch_bounds__(256)
bgemm_kernel(const __nv_bfloat16* __restrict__ W, const __nv_bfloat16* __restrict__ Z,
             const float* __restrict__ bias, const float* __restrict__ res,
             float* __restrict__ O, int M, int K, int P)
{
    extern __shared__ __align__(16) char dsm[];

    const int b  = blockIdx.z;
    const __nv_bfloat16* Zb = Z + (size_t)b * K * P;
    float*       Ob = O + (size_t)b * M * P;
    const float* Rb = res ? res + (size_t)b * M * P : nullptr;

    const int m0 = blockIdx.y * 128;
    const int n0 = blockIdx.x * 128;
    const int tid  = threadIdx.x;
    const int lane = tid & 31;
    const int wid  = tid >> 5;
    const int wm = wid & 1;
    const int wn = wid >> 1;

    const uint32_t smem0 = sptr(dsm);
    // A stages at smem0 + s*AS_BYTES; B stages at smem0 + 3*AS_BYTES + s*BS_BYTES
    const uint32_t bbase0 = smem0 + GEMM_STAGES * AS_BYTES;

    const int a_r = tid >> 2;
    const int a_c = tid & 3;
    const int b_r = tid >> 4;
    const int b_c = tid & 15;

    float acc[4][4][4];
#pragma unroll
    for (int mt = 0; mt < 4; mt++)
#pragma unroll
        for (int nt = 0; nt < 4; nt++)
#pragma unroll
            for (int i = 0; i < 4; i++) acc[mt][nt][i] = 0.f;

    const int nk = K >> 5;

    // prologue: issue tiles 0 and 1
#pragma unroll
    for (int pt = 0; pt < 2; pt++) {
        const uint32_t as = smem0 + pt * AS_BYTES;
        const uint32_t bs = bbase0 + pt * BS_BYTES;
        const int k0 = pt * 32;
        cp16(as + (uint32_t)((a_r)      * AS_STRIDE + a_c * 8) * 2, W  + (size_t)(m0 + a_r)      * K + k0 + a_c * 8);
        cp16(as + (uint32_t)((a_r + 64) * AS_STRIDE + a_c * 8) * 2, W  + (size_t)(m0 + a_r + 64) * K + k0 + a_c * 8);
        cp16(bs + (uint32_t)((b_r)      * BS_STRIDE + b_c * 8) * 2, Zb + (size_t)(k0 + b_r)      * P + n0 + b_c * 8);
        cp16(bs + (uint32_t)((b_r + 16) * BS_STRIDE + b_c * 8) * 2, Zb + (size_t)(k0 + b_r + 16) * P + n0 + b_c * 8);
        cp_commit();
    }

    int s = 0;           // stage of tile kt
    for (int kt = 0; kt < nk; kt++) {
        if (kt + 1 < nk) cp_wait1(); else cp_wait0();
        __syncthreads();

        if (kt + 2 < nk) {
            int sp = s + 2; if (sp >= GEMM_STAGES) sp -= GEMM_STAGES;   // stage for tile kt+2
            const uint32_t as = smem0 + sp * AS_BYTES;
            const uint32_t bs = bbase0 + sp * BS_BYTES;
            const int k0 = (kt + 2) * 32;
            cp16(as + (uint32_t)((a_r)      * AS_STRIDE + a_c * 8) * 2, W  + (size_t)(m0 + a_r)      * K + k0 + a_c * 8);
            cp16(as + (uint32_t)((a_r + 64) * AS_STRIDE + a_c * 8) * 2, W  + (size_t)(m0 + a_r + 64) * K + k0 + a_c * 8);
            cp16(bs + (uint32_t)((b_r)      * BS_STRIDE + b_c * 8) * 2, Zb + (size_t)(k0 + b_r)      * P + n0 + b_c * 8);
            cp16(bs + (uint32_t)((b_r + 16) * BS_STRIDE + b_c * 8) * 2, Zb + (size_t)(k0 + b_r + 16) * P + n0 + b_c * 8);
            cp_commit();
        }

        const uint32_t as = smem0 + s * AS_BYTES;
        const uint32_t bs = bbase0 + s * BS_BYTES;

#pragma unroll
        for (int kk = 0; kk < 2; kk++) {
            const int k0 = kk * 16;
            uint32_t a[4][4];
            const uint32_t a_base = as + (uint32_t)(((wm * 64 + (lane & 15)) * AS_STRIDE) + k0 + (lane >> 4) * 8) * 2;
#pragma unroll
            for (int mt = 0; mt < 4; mt++)
                ldsmx4(a[mt], a_base + (uint32_t)(mt * 16 * AS_STRIDE) * 2);

            uint32_t bb[4][2];
            const uint32_t b_base = bs + (uint32_t)((k0 + (lane & 15)) * BS_STRIDE + wn * 32 + (lane >> 4) * 8) * 2;
            {
                uint32_t r[4];
                ldsmx4t(r, b_base);
                bb[0][0] = r[0]; bb[0][1] = r[1];
                bb[1][0] = r[2]; bb[1][1] = r[3];
                ldsmx4t(r, b_base + 16 * 2);
                bb[2][0] = r[0]; bb[2][1] = r[1];
                bb[3][0] = r[2]; bb[3][1] = r[3];
            }

#pragma unroll
            for (int mt = 0; mt < 4; mt++)
#pragma unroll
                for (int nt = 0; nt < 4; nt++)
                    mma16816(acc[mt][nt], a[mt], bb[nt]);
        }
        __syncthreads();
        if (++s == GEMM_STAGES) s = 0;
    }

#pragma unroll
    for (int mt = 0; mt < 4; mt++) {
        const int r0 = m0 + wm * 64 + mt * 16 + (lane >> 2);
        const int r1 = r0 + 8;
        const float bv0 = bias[r0];
        const float bv1 = bias[r1];
#pragma unroll
        for (int nt = 0; nt < 4; nt++) {
            const int col = n0 + wn * 32 + nt * 8 + (lane & 3) * 2;
            float2 v0 = make_float2(acc[mt][nt][0] + bv0, acc[mt][nt][1] + bv0);
            float2 v1 = make_float2(acc[mt][nt][2] + bv1, acc[mt][nt][3] + bv1);
            if (Rb) {
                float2 t0 = *(const float2*)&Rb[(size_t)r0 * P + col];
                float2 t1 = *(const float2*)&Rb[(size_t)r1 * P + col];
                v0.x += t0.x; v0.y += t0.y;
                v1.x += t1.x; v1.y += t1.y;
            }
            *(float2*)&Ob[(size_t)r0 * P + col] = v0;
            *(float2*)&Ob[(size_t)r1 * P + col] = v1;
        }
    }
}

// ---------------------------------------------------------------------------
// Correlation, 2-pixel y-blocking (round-5 proven version).
// Tile: 32 (w) x 16 (h) pixels; thread (tx,ty) handles pixels (2ty, tx) and
// (2ty+1, tx). Windows share 8 of 10 rows -> 90 smem reads / 162 FMAs.
// ---------------------------------------------------------------------------
#define CTW 32
#define CTH2 16
#define CWW (CTW + 2 * DD)    // 40
#define CWH (CTH2 + 2 * DD)   // 24
#define CCH 8
#define CPB (CINT / CSPLIT)   // 256

__global__ void __launch_bounds__(256, 1)
corr_kernel(const float* __restrict__ theta,
            const float* __restrict__ phi,
            float* __restrict__ pwpart)
{
    __shared__ float th_s[CCH * CTH2 * CTW];   // 16 KB
    __shared__ float ph_s[CCH * CWH * CWW];    // 30 KB

    const int z  = blockIdx.z;
    const int b  = z >> 1;
    const int ci = z & 1;
    const int ch0 = ci * CPB;
    const int w0 = blockIdx.x * CTW;
    const int h0 = blockIdx.y * CTH2;
    const int tid = threadIdx.x;
    const int tx = tid & 31;
    const int ty = tid >> 5;          // 0..7 -> pixel rows 2ty, 2ty+1

    const float* thb = theta + (size_t)b * CINT * PP;
    const float* phb = phi   + (size_t)b * CINT * PP;

    float accA[QQ], accB[QQ];
#pragma unroll
    for (int q = 0; q < QQ; q++) { accA[q] = 0.f; accB[q] = 0.f; }

    for (int c0 = ch0; c0 < ch0 + CPB; c0 += CCH) {
        // theta tile: CCH x 16 x 32 = 4096 floats
#pragma unroll
        for (int ii = 0; ii < (CCH * CTH2 * CTW) / 256; ii++) {
            const int i   = tid + ii * 256;
            const int cc  = i >> 9;
            const int rem = i & 511;
            th_s[i] = thb[(size_t)(c0 + cc) * PP + (h0 + (rem >> 5)) * WW + (w0 + (rem & 31))];
        }
        // phi window: CCH x 24 x 40 = 7680 floats, zero-padded
#pragma unroll
        for (int ii = 0; ii < (CCH * CWH * CWW) / 256; ii++) {
            const int i   = tid + ii * 256;
            const int cc  = i / (CWH * CWW);
            const int rem = i % (CWH * CWW);
            const int r   = rem / CWW;
            const int col = rem % CWW;
            const int hh = h0 - DD + r;
            const int ww = w0 - DD + col;
            float v = 0.f;
            if (hh >= 0 && hh < HH && ww >= 0 && ww < WW)
                v = phb[(size_t)(c0 + cc) * PP + hh * WW + ww];
            ph_s[i] = v;
        }
        __syncthreads();

#pragma unroll
        for (int cc = 0; cc < CCH; cc++) {
            const float t0 = th_s[cc * (CTH2 * CTW) + (2 * ty)     * CTW + tx];
            const float t1 = th_s[cc * (CTH2 * CTW) + (2 * ty + 1) * CTW + tx];
            const float* pr = &ph_s[cc * (CWH * CWW)];
#pragma unroll
            for (int rr = 0; rr < 10; rr++) {
                const float* row = &pr[(2 * ty + rr) * CWW + tx];
#pragma unroll
                for (int dx = 0; dx < 9; dx++) {
                    const float v = row[dx];
                    if (rr < 9) accA[rr * 9 + dx] += t0 * v;
                    if (rr >= 1) accB[(rr - 1) * 9 + dx] += t1 * v;
                }
            }
        }
        __syncthreads();
    }

    const int pixA = (h0 + 2 * ty) * WW + (w0 + tx);
    float* bp = pwpart + ((size_t)(ci * NB + b) * QQ) * PP;
#pragma unroll
    for (int q = 0; q < QQ; q++) {
        bp[(size_t)q * PP + pixA]      = accA[q];
        bp[(size_t)q * PP + pixA + WW] = accB[q];
    }
}

// ---------------------------------------------------------------------------
// Softmax over Q (sums the 2 channel-split partials, applies scale)
// ---------------------------------------------------------------------------
__global__ void __launch_bounds__(128)
softmax_kernel(const float* __restrict__ part, float* __restrict__ pw)
{
    const int t = blockIdx.x * 128 + threadIdx.x;
    const int b = t / PP;
    const int pix = t - b * PP;
    const size_t qp = (size_t)QQ * PP;
    const float scale = 256.0f / sqrtf((float)WW) / (float)CINT;

    float v[QQ];
    float m = -1e30f;
#pragma unroll
    for (int q = 0; q < QQ; q++) {
        const size_t off = (size_t)q * PP + pix;
        float s = part[(size_t)(0 * NB + b) * qp + off]
                + part[(size_t)(1 * NB + b) * qp + off];
        v[q] = s * scale;
        m = fmaxf(m, v[q]);
    }
    float s = 0.f;
#pragma unroll
    for (int q = 0; q < QQ; q++) { v[q] = __expf(v[q] - m); s += v[q]; }
    const float inv = 1.0f / s;
    float* pwb = pw + (size_t)b * qp + pix;
#pragma unroll
    for (int q = 0; q < QQ; q++) pwb[(size_t)q * PP] = v[q] * inv;
}

// ---------------------------------------------------------------------------
// Assemble, 2-pixel y-blocking (round-5 proven version): bf16 output.
// ---------------------------------------------------------------------------
__global__ void __launch_bounds__(256, 1)
assemble_kernel(const float* __restrict__ pw,
                const float* __restrict__ g,
                __nv_bfloat16* __restrict__ y)
{
    __shared__ float gs[CCH * CWH * CWW];   // 30 KB

    const int z  = blockIdx.z;
    const int b  = z >> 3;
    const int c0base = (z & 7) * (CINT / ASPLIT); // 64 channels
    const int w0 = blockIdx.x * CTW;
    const int h0 = blockIdx.y * CTH2;
    const int tid = threadIdx.x;
    const int tx = tid & 31;
    const int ty = tid >> 5;

    const float* gb  = g  + (size_t)b * CINT * PP;
    const float* pwb = pw + (size_t)b * QQ * PP;
    __nv_bfloat16* yb = y + (size_t)b * CINT * PP;

    const int pixA = (h0 + 2 * ty) * WW + (w0 + tx);
    const int pixB = pixA + WW;

    float rpwA[QQ], rpwB[QQ];
#pragma unroll
    for (int q = 0; q < QQ; q++) {
        rpwA[q] = pwb[(size_t)q * PP + pixA];
        rpwB[q] = pwb[(size_t)q * PP + pixB];
    }

    for (int c0 = c0base; c0 < c0base + CINT / ASPLIT; c0 += CCH) {
#pragma unroll
        for (int ii = 0; ii < (CCH * CWH * CWW) / 256; ii++) {
            const int i   = tid + ii * 256;
            const int cc  = i / (CWH * CWW);
            const int rem = i % (CWH * CWW);
            const int r   = rem / CWW;
            const int col = rem % CWW;
            const int hh = h0 - DD + r;
            const int ww = w0 - DD + col;
            float v = 0.f;
            if (hh >= 0 && hh < HH && ww >= 0 && ww < WW)
                v = gb[(size_t)(c0 + cc) * PP + hh * WW + ww];
            gs[i] = v;
        }
        __syncthreads();

#pragma unroll
        for (int cc = 0; cc < CCH; cc++) {
            const float* gr = &gs[cc * (CWH * CWW)];
            float aA = 0.f, aB = 0.f;
#pragma unroll
            for (int rr = 0; rr < 10; rr++) {
                const float* row = &gr[(2 * ty + rr) * CWW + tx];
#pragma unroll
                for (int dx = 0; dx < 9; dx++) {
                    const float v = row[dx];
                    if (rr < 9) aA += rpwA[rr * 9 + dx] * v;
                    if (rr >= 1) aB += rpwB[(rr - 1) * 9 + dx] * v;
                }
            }
            yb[(size_t)(c0 + cc) * PP + pixA] = __float2bfloat16(aA);
            yb[(size_t)(c0 + cc) * PP + pixB] = __float2bfloat16(aB);
        }
        __syncthreads();
    }
}

// ---------------------------------------------------------------------------
// Launch
// ---------------------------------------------------------------------------
extern "C" void kernel_launch(void* const* d_in, const int* in_sizes, int n_in,
                              void* d_out, int out_size)
{
    (void)in_sizes; (void)n_in; (void)out_size;

    const float* x       = (const float*)d_in[0];
    const float* x_ref   = (const float*)d_in[1];
    const float* w_g     = (const float*)d_in[2];
    const float* b_g     = (const float*)d_in[3];
    const float* w_theta = (const float*)d_in[4];
    const float* b_theta = (const float*)d_in[5];
    const float* w_phi   = (const float*)d_in[6];
    const float* b_phi   = (const float*)d_in[7];
    const float* w_out   = (const float*)d_in[8];
    const float* b_out   = (const float*)d_in[9];
    float* out = (float*)d_out;

    __nv_bfloat16 *xb, *xrefb, *wb, *yb;
    float *theta, *gbuf, *phi, *pwpart, *pw;
    cudaGetSymbolAddress((void**)&xb,     g_xb);
    cudaGetSymbolAddress((void**)&xrefb,  g_xrefb);
    cudaGetSymbolAddress((void**)&wb,     g_wb);
    cudaGetSymbolAddress((void**)&theta,  g_theta);
    cudaGetSymbolAddress((void**)&gbuf,   g_g);
    cudaGetSymbolAddress((void**)&phi,    g_phi);
    cudaGetSymbolAddress((void**)&pwpart, g_pwpart);
    cudaGetSymbolAddress((void**)&pw,     g_pw);
    cudaGetSymbolAddress((void**)&yb,     g_yb);

    cudaFuncSetAttribute(bgemm_kernel, cudaFuncAttributeMaxDynamicSharedMemorySize, GEMM_SMEM);

    const int WSZ = CINT * CIN;
    __nv_bfloat16* wtb = wb + 0 * WSZ;
    __nv_bfloat16* wgb = wb + 1 * WSZ;
    __nv_bfloat16* wpb = wb + 2 * WSZ;
    __nv_bfloat16* wob = wb + 3 * WSZ;

    // conversions (2 launches)
    const int nx = NB * CIN * PP;
    dim3 cxg(nx / (256 * 8), 1, 2);
    convx_kernel<<<cxg, 256>>>(x, x_ref, xb, xrefb);
    dim3 cwg(WSZ / (256 * 8), 1, 4);
    convw_kernel<<<cwg, 256>>>(w_theta, w_g, w_phi, w_out, wb);

    // 1x1 convs (tensor-core GEMMs, 3-stage pipeline)
    dim3 blk(256);
    dim3 gg1(PP / 128, CINT / 128, NB);     // (72, 4, 4)
    bgemm_kernel<<<gg1, blk, GEMM_SMEM>>>(wtb, xb,    b_theta, nullptr, theta, CINT, CIN, PP);
    bgemm_kernel<<<gg1, blk, GEMM_SMEM>>>(wgb, xrefb, b_g,     nullptr, gbuf,  CINT, CIN, PP);
    bgemm_kernel<<<gg1, blk, GEMM_SMEM>>>(wpb, xrefb, b_phi,   nullptr, phi,   CINT, CIN, PP);

    // correlation partials + softmax
    dim3 cg(WW / CTW, HH / CTH2, NB * CSPLIT);   // (3, 6, 8) = 144 blocks
    corr_kernel<<<cg, blk>>>(theta, phi, pwpart);
    softmax_kernel<<<(NB * PP) / 128, 128>>>(pwpart, pw);

    // assemble (bf16 output)
    dim3 ag(WW / CTW, HH / CTH2, NB * ASPLIT);   // (3, 6, 32) = 576 blocks
    assemble_kernel<<<ag, blk>>>(pw, gbuf, yb);

    // final conv + residual
    dim3 gg2(PP / 128, CIN / 128, NB);           // (72, 8, 4)
    bgemm_kernel<<<gg2, blk, GEMM_SMEM>>>(wob, yb, b_out, x, out, CIN, CINT, PP);
}

// round 11
// speedup vs baseline: 1.6950x; 1.2062x over previous
#include <cuda_runtime.h>
#include <cuda_bf16.h>
#include <math.h>
#include <stdint.h>

// Problem constants
#define NB    4
#define CIN   1024
#define CINT  512
#define HH    96
#define WW    96
#define PP    (HH * WW)      // 9216
#define DD    4
#define QQ    81
#define CSPLIT 2             // corr channel split
#define ASPLIT 8             // assemble channel split

// ---------------------------------------------------------------------------
// Scratch (device globals; no allocation allowed)
// ---------------------------------------------------------------------------
__device__ __align__(128) __nv_bfloat16 g_xb   [NB * CIN  * PP];
__device__ __align__(128) __nv_bfloat16 g_xrefb[NB * CIN  * PP];
__device__ __align__(128) __nv_bfloat16 g_wb   [4 * CINT * CIN];   // theta,g,phi,out
__device__ __align__(128) float g_theta [NB * CINT * PP];
__device__ __align__(128) float g_g     [NB * CINT * PP];
__device__ __align__(128) float g_phi   [NB * CINT * PP];
__device__ __align__(128) float g_pwpart[CSPLIT * NB * QQ * PP];
__device__ __align__(128) float g_pw    [NB * QQ * PP];
__device__ __align__(128) __nv_bfloat16 g_yb   [NB * CINT * PP];

// ---------------------------------------------------------------------------
// Helpers (legacy path: cp.async + ldmatrix + mma.sync; no tcgen05 — the
// toolchain targets sm_103 without the 'a' feature set)
// ---------------------------------------------------------------------------
__device__ __forceinline__ uint32_t sptr(const void* p) {
    return (uint32_t)__cvta_generic_to_shared(p);
}
__device__ __forceinline__ void cp16(uint32_t dst, const void* src) {
    asm volatile("cp.async.cg.shared.global [%0], [%1], 16;" :: "r"(dst), "l"(src));
}
__device__ __forceinline__ void cp_commit() {
    asm volatile("cp.async.commit_group;");
}
__device__ __forceinline__ void cp_wait0() {
    asm volatile("cp.async.wait_group 0;");
}
__device__ __forceinline__ void cp_wait1() {
    asm volatile("cp.async.wait_group 1;");
}
__device__ __forceinline__ void ldsmx4(uint32_t* r, uint32_t addr) {
    asm volatile("ldmatrix.sync.aligned.m8n8.x4.shared.b16 {%0,%1,%2,%3}, [%4];"
                 : "=r"(r[0]), "=r"(r[1]), "=r"(r[2]), "=r"(r[3]) : "r"(addr));
}
__device__ __forceinline__ void ldsmx4t(uint32_t* r, uint32_t addr) {
    asm volatile("ldmatrix.sync.aligned.m8n8.x4.trans.shared.b16 {%0,%1,%2,%3}, [%4];"
                 : "=r"(r[0]), "=r"(r[1]), "=r"(r[2]), "=r"(r[3]) : "r"(addr));
}
__device__ __forceinline__ void mma16816(float* c, const uint32_t* a, const uint32_t* b) {
    asm volatile("mma.sync.aligned.m16n8k16.row.col.f32.bf16.bf16.f32 "
                 "{%0,%1,%2,%3}, {%4,%5,%6,%7}, {%8,%9}, {%0,%1,%2,%3};"
                 : "+f"(c[0]), "+f"(c[1]), "+f"(c[2]), "+f"(c[3])
                 : "r"(a[0]), "r"(a[1]), "r"(a[2]), "r"(a[3]), "r"(b[0]), "r"(b[1]));
}

// ---------------------------------------------------------------------------
// Merged conversions: activations (z: 0=x, 1=x_ref) and weights (z: 0..3)
// ---------------------------------------------------------------------------
__global__ void __launch_bounds__(256)
convx_kernel(const float* __restrict__ x, const float* __restrict__ xref,
             __nv_bfloat16* __restrict__ xb, __nv_bfloat16* __restrict__ xrefb)
{
    const float* in = blockIdx.z ? xref : x;
    __nv_bfloat16* out = blockIdx.z ? xrefb : xb;
    int i = (blockIdx.x * 256 + threadIdx.x) * 8;
    float4 v0 = *(const float4*)(in + i);
    float4 v1 = *(const float4*)(in + i + 4);
    __nv_bfloat162 o[4];
    o[0] = __floats2bfloat162_rn(v0.x, v0.y);
    o[1] = __floats2bfloat162_rn(v0.z, v0.w);
    o[2] = __floats2bfloat162_rn(v1.x, v1.y);
    o[3] = __floats2bfloat162_rn(v1.z, v1.w);
    *(uint4*)(out + i) = *(const uint4*)o;
}

__global__ void __launch_bounds__(256)
convw_kernel(const float* __restrict__ w0, const float* __restrict__ w1,
             const float* __restrict__ w2, const float* __restrict__ w3,
             __nv_bfloat16* __restrict__ out)
{
    const int z = blockIdx.z;
    const float* in = (z == 0) ? w0 : (z == 1) ? w1 : (z == 2) ? w2 : w3;
    __nv_bfloat16* o = out + (size_t)z * (CINT * CIN);
    int i = (blockIdx.x * 256 + threadIdx.x) * 8;
    float4 v0 = *(const float4*)(in + i);
    float4 v1 = *(const float4*)(in + i + 4);
    __nv_bfloat162 p[4];
    p[0] = __floats2bfloat162_rn(v0.x, v0.y);
    p[1] = __floats2bfloat162_rn(v0.z, v0.w);
    p[2] = __floats2bfloat162_rn(v1.x, v1.y);
    p[3] = __floats2bfloat162_rn(v1.z, v1.w);
    *(uint4*)(o + i) = *(const uint4*)p;
}

// ---------------------------------------------------------------------------
// bf16 tensor-core GEMM (mma.sync), 3-stage cp.async pipeline, ONE barrier
// per k-tile (the top-of-iteration barrier orders stage reuse; the prefetch
// target is the stage read in the PREVIOUS iteration).
// ---------------------------------------------------------------------------
#define AS_STRIDE 40
#define BS_STRIDE 136
#define AS_ELEMS (128 * AS_STRIDE)
#define BS_ELEMS (32 * BS_STRIDE)
#define AS_BYTES (AS_ELEMS * 2)
#define BS_BYTES (BS_ELEMS * 2)
#define GEMM_STAGES 3
#define GEMM_SMEM (GEMM_STAGES * (AS_BYTES + BS_BYTES))   // 56832

__global__ void __launch_bounds__(256)
bgemm_kernel(const __nv_bfloat16* __restrict__ W, const __nv_bfloat16* __restrict__ Z,
             const float* __restrict__ bias, const float* __restrict__ res,
             float* __restrict__ O, int M, int K, int P)
{
    extern __shared__ __align__(16) char dsm[];

    const int b  = blockIdx.z;
    const __nv_bfloat16* Zb = Z + (size_t)b * K * P;
    float*       Ob = O + (size_t)b * M * P;
    const float* Rb = res ? res + (size_t)b * M * P : nullptr;

    const int m0 = blockIdx.y * 128;
    const int n0 = blockIdx.x * 128;
    const int tid  = threadIdx.x;
    const int lane = tid & 31;
    const int wid  = tid >> 5;
    const int wm = wid & 1;
    const int wn = wid >> 1;

    const uint32_t smem0 = sptr(dsm);
    const uint32_t bbase0 = smem0 + GEMM_STAGES * AS_BYTES;

    const int a_r = tid >> 2;
    const int a_c = tid & 3;
    const int b_r = tid >> 4;
    const int b_c = tid & 15;

    float acc[4][4][4];
#pragma unroll
    for (int mt = 0; mt < 4; mt++)
#pragma unroll
        for (int nt = 0; nt < 4; nt++)
#pragma unroll
            for (int i = 0; i < 4; i++) acc[mt][nt][i] = 0.f;

    const int nk = K >> 5;

#pragma unroll
    for (int pt = 0; pt < 2; pt++) {
        const uint32_t as = smem0 + pt * AS_BYTES;
        const uint32_t bs = bbase0 + pt * BS_BYTES;
        const int k0 = pt * 32;
        cp16(as + (uint32_t)((a_r)      * AS_STRIDE + a_c * 8) * 2, W  + (size_t)(m0 + a_r)      * K + k0 + a_c * 8);
        cp16(as + (uint32_t)((a_r + 64) * AS_STRIDE + a_c * 8) * 2, W  + (size_t)(m0 + a_r + 64) * K + k0 + a_c * 8);
        cp16(bs + (uint32_t)((b_r)      * BS_STRIDE + b_c * 8) * 2, Zb + (size_t)(k0 + b_r)      * P + n0 + b_c * 8);
        cp16(bs + (uint32_t)((b_r + 16) * BS_STRIDE + b_c * 8) * 2, Zb + (size_t)(k0 + b_r + 16) * P + n0 + b_c * 8);
        cp_commit();
    }

    int s = 0;
    for (int kt = 0; kt < nk; kt++) {
        if (kt + 1 < nk) cp_wait1(); else cp_wait0();
        __syncthreads();

        if (kt + 2 < nk) {
            int sp = s + 2; if (sp >= GEMM_STAGES) sp -= GEMM_STAGES;
            const uint32_t as = smem0 + sp * AS_BYTES;
            const uint32_t bs = bbase0 + sp * BS_BYTES;
            const int k0 = (kt + 2) * 32;
            cp16(as + (uint32_t)((a_r)      * AS_STRIDE + a_c * 8) * 2, W  + (size_t)(m0 + a_r)      * K + k0 + a_c * 8);
            cp16(as + (uint32_t)((a_r + 64) * AS_STRIDE + a_c * 8) * 2, W  + (size_t)(m0 + a_r + 64) * K + k0 + a_c * 8);
            cp16(bs + (uint32_t)((b_r)      * BS_STRIDE + b_c * 8) * 2, Zb + (size_t)(k0 + b_r)      * P + n0 + b_c * 8);
            cp16(bs + (uint32_t)((b_r + 16) * BS_STRIDE + b_c * 8) * 2, Zb + (size_t)(k0 + b_r + 16) * P + n0 + b_c * 8);
            cp_commit();
        }

        const uint32_t as = smem0 + s * AS_BYTES;
        const uint32_t bs = bbase0 + s * BS_BYTES;

#pragma unroll
        for (int kk = 0; kk < 2; kk++) {
            const int k0 = kk * 16;
            uint32_t a[4][4];
            const uint32_t a_base = as + (uint32_t)(((wm * 64 + (lane & 15)) * AS_STRIDE) + k0 + (lane >> 4) * 8) * 2;
#pragma unroll
            for (int mt = 0; mt < 4; mt++)
                ldsmx4(a[mt], a_base + (uint32_t)(mt * 16 * AS_STRIDE) * 2);

            uint32_t bb[4][2];
            const uint32_t b_base = bs + (uint32_t)((k0 + (lane & 15)) * BS_STRIDE + wn * 32 + (lane >> 4) * 8) * 2;
            {
                uint32_t r[4];
                ldsmx4t(r, b_base);
                bb[0][0] = r[0]; bb[0][1] = r[1];
                bb[1][0] = r[2]; bb[1][1] = r[3];
                ldsmx4t(r, b_base + 16 * 2);
                bb[2][0] = r[0]; bb[2][1] = r[1];
                bb[3][0] = r[2]; bb[3][1] = r[3];
            }

#pragma unroll
            for (int mt = 0; mt < 4; mt++)
#pragma unroll
                for (int nt = 0; nt < 4; nt++)
                    mma16816(acc[mt][nt], a[mt], bb[nt]);
        }
        if (++s == GEMM_STAGES) s = 0;
    }

#pragma unroll
    for (int mt = 0; mt < 4; mt++) {
        const int r0 = m0 + wm * 64 + mt * 16 + (lane >> 2);
        const int r1 = r0 + 8;
        const float bv0 = bias[r0];
        const float bv1 = bias[r1];
#pragma unroll
        for (int nt = 0; nt < 4; nt++) {
            const int col = n0 + wn * 32 + nt * 8 + (lane & 3) * 2;
            float2 v0 = make_float2(acc[mt][nt][0] + bv0, acc[mt][nt][1] + bv0);
            float2 v1 = make_float2(acc[mt][nt][2] + bv1, acc[mt][nt][3] + bv1);
            if (Rb) {
                float2 t0 = *(const float2*)&Rb[(size_t)r0 * P + col];
                float2 t1 = *(const float2*)&Rb[(size_t)r1 * P + col];
                v0.x += t0.x; v0.y += t0.y;
                v1.x += t1.x; v1.y += t1.y;
            }
            *(float2*)&Ob[(size_t)r0 * P + col] = v0;
            *(float2*)&Ob[(size_t)r1 * P + col] = v1;
        }
    }
}

// ---------------------------------------------------------------------------
// Correlation, 2-pixel y-blocking + register-prefetch pipeline (CCH=4).
// Per chunk: STS(c) -> bar -> LDG(c+1)->regs -> compute(c) -> bar.
// LDG latency hidden behind ~650 FMA of compute.
// ---------------------------------------------------------------------------
#define CTW 32
#define CTH2 16
#define CWW (CTW + 2 * DD)    // 40
#define CWH (CTH2 + 2 * DD)   // 24
#define CCH 4
#define CPB (CINT / CSPLIT)   // 256
#define TH_F4 ((CCH * CTH2 * CTW) / 4)   // 512 float4
#define PH_F4 ((CCH * CWH * CWW) / 4)    // 960 float4

__global__ void __launch_bounds__(256, 1)
corr_kernel(const float* __restrict__ theta,
            const float* __restrict__ phi,
            float* __restrict__ pwpart)
{
    __shared__ __align__(16) float th_s[CCH * CTH2 * CTW];   // 8 KB
    __shared__ __align__(16) float ph_s[CCH * CWH * CWW];    // 15 KB

    const int z  = blockIdx.z;
    const int b  = z >> 1;
    const int ci = z & 1;
    const int ch0 = ci * CPB;
    const int w0 = blockIdx.x * CTW;
    const int h0 = blockIdx.y * CTH2;
    const int tid = threadIdx.x;
    const int tx = tid & 31;
    const int ty = tid >> 5;          // 0..7 -> pixel rows 2ty, 2ty+1

    const float* thb = theta + (size_t)b * CINT * PP;
    const float* phb = phi   + (size_t)b * CINT * PP;

    float accA[QQ], accB[QQ];
#pragma unroll
    for (int q = 0; q < QQ; q++) { accA[q] = 0.f; accB[q] = 0.f; }

    float4 thr[2];    // theta regs: idx4 = tid*2+j
    float4 phr[4];    // phi regs: t = tid + j*256 (t < 960)

    // ---- load chunk into registers ----
#define CORR_LOAD(c0)                                                          \
    {                                                                          \
        _Pragma("unroll")                                                      \
        for (int j = 0; j < 2; j++) {                                          \
            const int idx4 = tid * 2 + j;                                      \
            const int cc  = idx4 >> 7;          /* 128 f4 per channel */       \
            const int rem = idx4 & 127;                                        \
            const int r   = rem >> 3;                                          \
            const int cg  = rem & 7;                                           \
            thr[j] = *(const float4*)&thb[(size_t)((c0) + cc) * PP +           \
                                          (h0 + r) * WW + w0 + cg * 4];        \
        }                                                                      \
        _Pragma("unroll")                                                      \
        for (int j = 0; j < 4; j++) {                                          \
            const int t = tid + j * 256;                                       \
            if (t < PH_F4) {                                                   \
                const int cc  = t / 240;        /* 240 f4 per channel */       \
                const int rem = t - cc * 240;                                  \
                const int r   = rem / 10;       /* 10 f4 per row */            \
                const int cg  = rem - r * 10;                                  \
                const int hh   = h0 - DD + r;                                  \
                const int gcol = w0 - DD + cg * 4;                             \
                float4 v = make_float4(0.f, 0.f, 0.f, 0.f);                    \
                if (hh >= 0 && hh < HH && gcol >= 0 && gcol < WW)              \
                    v = *(const float4*)&phb[(size_t)((c0) + cc) * PP +        \
                                             hh * WW + gcol];                  \
                phr[j] = v;                                                    \
            }                                                                  \
        }                                                                      \
    }

    CORR_LOAD(ch0);

    const int nch = CPB / CCH;   // 64 chunks
    for (int c = 0; c < nch; c++) {
        // store registers (chunk c) to smem
#pragma unroll
        for (int j = 0; j < 2; j++) ((float4*)th_s)[tid * 2 + j] = thr[j];
#pragma unroll
        for (int j = 0; j < 4; j++) {
            const int t = tid + j * 256;
            if (t < PH_F4) ((float4*)ph_s)[t] = phr[j];
        }
        __syncthreads();

        // prefetch chunk c+1 into registers (lands during compute)
        if (c + 1 < nch) CORR_LOAD(ch0 + (c + 1) * CCH);

        // compute chunk c
#pragma unroll
        for (int cc = 0; cc < CCH; cc++) {
            const float t0 = th_s[cc * (CTH2 * CTW) + (2 * ty)     * CTW + tx];
            const float t1 = th_s[cc * (CTH2 * CTW) + (2 * ty + 1) * CTW + tx];
            const float* pr = &ph_s[cc * (CWH * CWW)];
#pragma unroll
            for (int rr = 0; rr < 10; rr++) {
                const float* row = &pr[(2 * ty + rr) * CWW + tx];
#pragma unroll
                for (int dx = 0; dx < 9; dx++) {
                    const float v = row[dx];
                    if (rr < 9) accA[rr * 9 + dx] += t0 * v;
                    if (rr >= 1) accB[(rr - 1) * 9 + dx] += t1 * v;
                }
            }
        }
        __syncthreads();
    }
#undef CORR_LOAD

    const int pixA = (h0 + 2 * ty) * WW + (w0 + tx);
    float* bp = pwpart + ((size_t)(ci * NB + b) * QQ) * PP;
#pragma unroll
    for (int q = 0; q < QQ; q++) {
        bp[(size_t)q * PP + pixA]      = accA[q];
        bp[(size_t)q * PP + pixA + WW] = accB[q];
    }
}

// ---------------------------------------------------------------------------
// Softmax over Q (sums the 2 channel-split partials, applies scale)
// ---------------------------------------------------------------------------
__global__ void __launch_bounds__(128)
softmax_kernel(const float* __restrict__ part, float* __restrict__ pw)
{
    const int t = blockIdx.x * 128 + threadIdx.x;
    const int b = t / PP;
    const int pix = t - b * PP;
    const size_t qp = (size_t)QQ * PP;
    const float scale = 256.0f / sqrtf((float)WW) / (float)CINT;

    float v[QQ];
    float m = -1e30f;
#pragma unroll
    for (int q = 0; q < QQ; q++) {
        const size_t off = (size_t)q * PP + pix;
        float s = part[(size_t)(0 * NB + b) * qp + off]
                + part[(size_t)(1 * NB + b) * qp + off];
        v[q] = s * scale;
        m = fmaxf(m, v[q]);
    }
    float s = 0.f;
#pragma unroll
    for (int q = 0; q < QQ; q++) { v[q] = __expf(v[q] - m); s += v[q]; }
    const float inv = 1.0f / s;
    float* pwb = pw + (size_t)b * qp + pix;
#pragma unroll
    for (int q = 0; q < QQ; q++) pwb[(size_t)q * PP] = v[q] * inv;
}

// ---------------------------------------------------------------------------
// Assemble, 2-pixel y-blocking + register-prefetch pipeline (CCH=4).
// ---------------------------------------------------------------------------
__global__ void __launch_bounds__(256, 1)
assemble_kernel(const float* __restrict__ pw,
                const float* __restrict__ g,
                __nv_bfloat16* __restrict__ y)
{
    __shared__ __align__(16) float gs[CCH * CWH * CWW];   // 15 KB

    const int z  = blockIdx.z;
    const int b  = z >> 3;
    const int c0base = (z & 7) * (CINT / ASPLIT); // 64 channels
    const int w0 = blockIdx.x * CTW;
    const int h0 = blockIdx.y * CTH2;
    const int tid = threadIdx.x;
    const int tx = tid & 31;
    const int ty = tid >> 5;

    const float* gb  = g  + (size_t)b * CINT * PP;
    const float* pwb = pw + (size_t)b * QQ * PP;
    __nv_bfloat16* yb = y + (size_t)b * CINT * PP;

    const int pixA = (h0 + 2 * ty) * WW + (w0 + tx);
    const int pixB = pixA + WW;

    float rpwA[QQ], rpwB[QQ];
#pragma unroll
    for (int q = 0; q < QQ; q++) {
        rpwA[q] = pwb[(size_t)q * PP + pixA];
        rpwB[q] = pwb[(size_t)q * PP + pixB];
    }

    float4 gr4[4];

#define ASM_LOAD(c0)                                                           \
    {                                                                          \
        _Pragma("unroll")                                                      \
        for (int j = 0; j < 4; j++) {                                          \
            const int t = tid + j * 256;                                       \
            if (t < PH_F4) {                                                   \
                const int cc  = t / 240;                                       \
                const int rem = t - cc * 240;                                  \
                const int r   = rem / 10;                                      \
                const int cg  = rem - r * 10;                                  \
                const int hh   = h0 - DD + r;                                  \
                const int gcol = w0 - DD + cg * 4;                             \
                float4 v = make_float4(0.f, 0.f, 0.f, 0.f);                    \
                if (hh >= 0 && hh < HH && gcol >= 0 && gcol < WW)              \
                    v = *(const float4*)&gb[(size_t)((c0) + cc) * PP +         \
                                            hh * WW + gcol];                   \
                gr4[j] = v;                                                    \
            }                                                                  \
        }                                                                      \
    }

    ASM_LOAD(c0base);

    const int nch = (CINT / ASPLIT) / CCH;   // 16 chunks
    for (int c = 0; c < nch; c++) {
#pragma unroll
        for (int j = 0; j < 4; j++) {
            const int t = tid + j * 256;
            if (t < PH_F4) ((float4*)gs)[t] = gr4[j];
        }
        __syncthreads();

        if (c + 1 < nch) ASM_LOAD(c0base + (c + 1) * CCH);

        const int c0 = c0base + c * CCH;
#pragma unroll
        for (int cc = 0; cc < CCH; cc++) {
            const float* grp = &gs[cc * (CWH * CWW)];
            float aA = 0.f, aB = 0.f;
#pragma unroll
            for (int rr = 0; rr < 10; rr++) {
                const float* row = &grp[(2 * ty + rr) * CWW + tx];
#pragma unroll
                for (int dx = 0; dx < 9; dx++) {
                    const float v = row[dx];
                    if (rr < 9) aA += rpwA[rr * 9 + dx] * v;
                    if (rr >= 1) aB += rpwB[(rr - 1) * 9 + dx] * v;
                }
            }
            yb[(size_t)(c0 + cc) * PP + pixA] = __float2bfloat16(aA);
            yb[(size_t)(c0 + cc) * PP + pixB] = __float2bfloat16(aB);
        }
        __syncthreads();
    }
#undef ASM_LOAD
}

// ---------------------------------------------------------------------------
// Launch
// ---------------------------------------------------------------------------
extern "C" void kernel_launch(void* const* d_in, const int* in_sizes, int n_in,
                              void* d_out, int out_size)
{
    (void)in_sizes; (void)n_in; (void)out_size;

    const float* x       = (const float*)d_in[0];
    const float* x_ref   = (const float*)d_in[1];
    const float* w_g     = (const float*)d_in[2];
    const float* b_g     = (const float*)d_in[3];
    const float* w_theta = (const float*)d_in[4];
    const float* b_theta = (const float*)d_in[5];
    const float* w_phi   = (const float*)d_in[6];
    const float* b_phi   = (const float*)d_in[7];
    const float* w_out   = (const float*)d_in[8];
    const float* b_out   = (const float*)d_in[9];
    float* out = (float*)d_out;

    __nv_bfloat16 *xb, *xrefb, *wb, *yb;
    float *theta, *gbuf, *phi, *pwpart, *pw;
    cudaGetSymbolAddress((void**)&xb,     g_xb);
    cudaGetSymbolAddress((void**)&xrefb,  g_xrefb);
    cudaGetSymbolAddress((void**)&wb,     g_wb);
    cudaGetSymbolAddress((void**)&theta,  g_theta);
    cudaGetSymbolAddress((void**)&gbuf,   g_g);
    cudaGetSymbolAddress((void**)&phi,    g_phi);
    cudaGetSymbolAddress((void**)&pwpart, g_pwpart);
    cudaGetSymbolAddress((void**)&pw,     g_pw);
    cudaGetSymbolAddress((void**)&yb,     g_yb);

    cudaFuncSetAttribute(bgemm_kernel, cudaFuncAttributeMaxDynamicSharedMemorySize, GEMM_SMEM);

    const int WSZ = CINT * CIN;
    __nv_bfloat16* wtb = wb + 0 * WSZ;
    __nv_bfloat16* wgb = wb + 1 * WSZ;
    __nv_bfloat16* wpb = wb + 2 * WSZ;
    __nv_bfloat16* wob = wb + 3 * WSZ;

    // conversions (2 launches)
    const int nx = NB * CIN * PP;
    dim3 cxg(nx / (256 * 8), 1, 2);
    convx_kernel<<<cxg, 256>>>(x, x_ref, xb, xrefb);
    dim3 cwg(WSZ / (256 * 8), 1, 4);
    convw_kernel<<<cwg, 256>>>(w_theta, w_g, w_phi, w_out, wb);

    // 1x1 convs (tensor-core GEMMs, 3-stage pipeline, single-barrier loop)
    dim3 blk(256);
    dim3 gg1(PP / 128, CINT / 128, NB);     // (72, 4, 4)
    bgemm_kernel<<<gg1, blk, GEMM_SMEM>>>(wtb, xb,    b_theta, nullptr, theta, CINT, CIN, PP);
    bgemm_kernel<<<gg1, blk, GEMM_SMEM>>>(wgb, xrefb, b_g,     nullptr, gbuf,  CINT, CIN, PP);
    bgemm_kernel<<<gg1, blk, GEMM_SMEM>>>(wpb, xrefb, b_phi,   nullptr, phi,   CINT, CIN, PP);

    // correlation partials + softmax
    dim3 cg(WW / CTW, HH / CTH2, NB * CSPLIT);   // (3, 6, 8) = 144 blocks
    corr_kernel<<<cg, blk>>>(theta, phi, pwpart);
    softmax_kernel<<<(NB * PP) / 128, 128>>>(pwpart, pw);

    // assemble (bf16 output)
    dim3 ag(WW / CTW, HH / CTH2, NB * ASPLIT);   // (3, 6, 32) = 576 blocks
    assemble_kernel<<<ag, blk>>>(pw, gbuf, yb);

    // final conv + residual
    dim3 gg2(PP / 128, CIN / 128, NB);           // (72, 8, 4)
    bgemm_kernel<<<gg2, blk, GEMM_SMEM>>>(wob, yb, b_out, x, out, CIN, CINT, PP);
}